// round 8
// baseline (speedup 1.0000x reference)
#include <cuda_runtime.h>
#include <cstdint>

typedef unsigned long long ull;

#define B_   1024
#define T_   1024
#define H_   128
#define C_   6
#define BPC  8            // batches per CTA
#define NCTA (B_/BPC)     // 128
#define NTHR 512          // 4 quarters x 128 j
#define KCQ  10           // smem-cached packA rows PER QUARTER (of its 32)
#define UCQ  (32-KCQ)     // 22 uncached rows per quarter

// ---------------- packed transposed weights (device globals) ---------------
__device__ float4 g_packA[H_*H_];   // [k][j] = (whh_r, whh_z, whh_n, w1)[j][k]
__device__ float  g_wu1T[H_*64];    // [k][j] = wu1[j][k], j<64
__device__ float4 g_packI[12*H_];   // [k][j] = (wih_r, wih_z, wih_n, 0)[j][k]

// ---------------- f32x2 helpers --------------------------------------------
__device__ __forceinline__ ull pk2(float a, float b){
    ull r; asm("mov.b64 %0, {%1,%2};" : "=l"(r) : "f"(a), "f"(b)); return r;
}
__device__ __forceinline__ void fma2(ull& d, ull a, ull b){
    asm("fma.rn.f32x2 %0, %1, %2, %3;" : "=l"(d) : "l"(a), "l"(b), "l"(d));
}
__device__ __forceinline__ void add2(ull& d, ull a){
    asm("add.rn.f32x2 %0, %1, %2;" : "=l"(d) : "l"(d), "l"(a));
}
__device__ __forceinline__ float2 up2(ull v){
    float2 r; asm("mov.b64 {%0,%1}, %2;" : "=f"(r.x), "=f"(r.y) : "l"(v)); return r;
}
__device__ __forceinline__ float sigf(float x){
    return __fdividef(1.f, 1.f + __expf(-x));
}
__device__ __forceinline__ float tanhfast(float x){
    float e = __expf(-2.f * fabsf(x));
    float t = __fdividef(1.f - e, 1.f + e);
    return copysignf(t, x);
}

// ---------------- weight pack pre-pass -------------------------------------
__global__ void pack_kernel(const float* __restrict__ w_ih, const float* __restrict__ w_hh,
                            const float* __restrict__ w1,   const float* __restrict__ wu1){
    int idx = blockIdx.x * blockDim.x + threadIdx.x;   // 0..16383
    int k = idx >> 7, j = idx & 127;
    g_packA[idx] = make_float4(w_hh[j*H_ + k], w_hh[(j+H_)*H_ + k],
                               w_hh[(j+2*H_)*H_ + k], w1[j*H_ + k]);
    if (j < 64)  g_wu1T[k*64 + j] = wu1[j*H_ + k];
    if (k < 12)  g_packI[k*H_ + j] = make_float4(w_ih[j*12 + k], w_ih[(j+H_)*12 + k],
                                                 w_ih[(j+2*H_)*12 + k], 0.f);
}

// ---------------- dynamic smem layout (float offsets) -----------------------
#define OFF_H     0        // sh_h  [128 j][8 b]
#define OFF_HD    1024     // sh_hd [128 j][8 b]
#define OFF_GIN   2048     // sh_gin[12][8]
#define OFF_HID1  2144     // sh_hid1[8 b][128 j]
#define OFF_HIDU  3168     // sh_hidu[8 b][64 j]
#define OFF_WU1   3680     // s_wu1 [128 k][64 j]
#define OFF_PI    11872    // s_pI  [12 k][128 j] float4
#define OFF_PART  18016    // s_part: [pair 4][src 3][quant 6][j 128] ull
#define OFF_WA    36448    // s_wA  [4*KCQ][128] float4
#define SMEM_FLOATS (OFF_WA + 4*KCQ*H_*4)
#define SMEM_BYTES  (SMEM_FLOATS * 4)   // 227,712 B <= 232,448

__global__ void __launch_bounds__(NTHR, 1) grud_kernel(
    const float* __restrict__ x,
    const float* __restrict__ x_mean,
    const float* __restrict__ dxw, const float* __restrict__ dxb,
    const float* __restrict__ dhw, const float* __restrict__ dhb,
    const float* __restrict__ b_ih, const float* __restrict__ b_hh,
    const float* __restrict__ b1,
    const float* __restrict__ w2,  const float* __restrict__ b2,
    const float* __restrict__ bu1,
    const float* __restrict__ wu2, const float* __restrict__ bu2,
    float* __restrict__ out)
{
    extern __shared__ float smem[];
    float*  sh_h   = smem + OFF_H;
    float*  sh_hd  = smem + OFF_HD;
    float*  sh_gin = smem + OFF_GIN;
    float*  sh_hid1= smem + OFF_HID1;
    float*  sh_hidu= smem + OFF_HIDU;
    float*  s_wu1  = smem + OFF_WU1;
    float4* s_pI   = (float4*)(smem + OFF_PI);
    ull*    s_part = (ull*)  (smem + OFF_PART);
    float4* s_wA   = (float4*)(smem + OFF_WA);

    const int tid = threadIdx.x;
    const int q   = tid >> 7;           // quarter: k in [32q, 32q+32)
    const int j   = tid & 127;
    const int b0  = blockIdx.x * BPC;

    // stage weights into shared (once)
    for (int i = tid; i < H_*64; i += NTHR) s_wu1[i] = g_wu1T[i];
    for (int i = tid; i < 12*H_; i += NTHR) s_pI[i]  = g_packI[i];
    for (int i = tid; i < 4*KCQ*H_; i += NTHR) {
        int s = i >> 7, jj = i & 127;
        int qq = s / KCQ, li = s - qq * KCQ;
        s_wA[i] = g_packA[(qq*32 + li)*H_ + jj];
    }

    // per-hidden-unit constants
    const float bihr = b_ih[j], bihz = b_ih[H_ + j], bihn = b_ih[2*H_ + j];
    const float bhhr = b_hh[j], bhhz = b_hh[H_ + j], bhhn = b_hh[2*H_ + j];
    const float b1j  = b1[j];
    const float bu1j = (j < 64) ? bu1[j] : 0.f;
    const float dhwj = dhw[j],  dhbj = dhb[j];

    // phase-A constants: tid<48 -> (batch ab, feature ac)
    const int ab = tid / 6, ac = tid - ab * 6;
    float xm = 0.f, axw = 0.f, axb = 0.f, b2c = 0.f;
    if (tid < 48) { xm = x_mean[ac]; axw = dxw[ac]; axb = dxb[ac]; b2c = b2[ac]; }
    // unc reducer: tid in [128,176) -> (ub, uc)
    const int ui = tid - 128;
    const int ub = ui / 6, uc = ui - ub * 6;
    float bu2c = 0.f;
    if (ui >= 0 && ui < 48) bu2c = bu2[uc];

    // rolling input pointers (advance by 13 per step)
    const float* xpA = x + (size_t)(b0 + ab) * T_ * 13;            // tid<48 path
    const float* pD0 = x + (size_t)(b0 + 2*q + 0) * T_ * 13 + 12;  // dt, own batch 0
    const float* pD1 = x + (size_t)(b0 + 2*q + 1) * T_ * 13 + 12;  // dt, own batch 1

    // precomputed exchange smem slot offsets (ull indices, loop-invariant)
    int wsOff[3], rsOff[3];
    {
        int w = 0;
        #pragma unroll
        for (int pp = 0; pp < 4; pp++) {
            if (pp == q) continue;
            int sidx = (q < pp) ? q : q - 1;
            wsOff[w++] = ((pp*3 + sidx)*6)*128 + j;
        }
        #pragma unroll
        for (int s = 0; s < 3; s++) rsOff[s] = ((q*3 + s)*6)*128 + j;
    }

    float running = 0.f, xlast = 0.f;
    float h_reg[2] = {0.f, 0.f};         // own batches: gb = 2q + lb

    // ---- preload step-0 inputs ---------------------------------------------
    float xv_c = 0.f, mm_c = 0.f, dtv_c = 0.f;
    if (tid < 48) { xv_c = xpA[ac]; mm_c = xpA[6 + ac]; dtv_c = xpA[12]; }
    float dt2_c[2] = { pD0[0], pD1[0] };

    __syncthreads();   // staged weights ready

    const int kg0 = q * 32;
    const float4* wAp = s_wA + (size_t)(q*KCQ)*H_ + j;              // cached rows
    const float4* gAp = g_packA + (size_t)(kg0 + KCQ)*H_ + j;       // uncached rows

    for (int t = 0; t <= T_; ++t) {
        // ---------------- Phase A: impute inputs for step t -----------------
        if (t < T_ && tid < 48) {
            bool obs = (mm_c > 0.5f);
            running = obs ? 0.f : (running + dtv_c);
            float gx = __expf(-fmaxf(running * axw + axb, 0.f));
            xlast = obs ? xv_c : xlast;
            float xhat = mm_c * xv_c + (1.f - mm_c) * (gx * xlast + (1.f - gx) * xm);
            sh_gin[ac * 8 + ab]       = xhat;
            sh_gin[(6 + ac) * 8 + ab] = mm_c;
        }

        // ---------------- Phase B: decay own 2 batches, publish -------------
        float hdec[2];
        #pragma unroll
        for (int lb = 0; lb < 2; lb++) {
            float g = __expf(-fmaxf(dt2_c[lb] * dhwj + dhbj, 0.f));
            hdec[lb] = h_reg[lb] * g;
        }
        *(float2*)(sh_h  + j*8 + 2*q) = make_float2(h_reg[0], h_reg[1]);
        *(float2*)(sh_hd + j*8 + 2*q) = make_float2(hdec[0], hdec[1]);
        __syncthreads();   // barA: gin + h/hd ready

        // ---------------- prefetch step t+1 inputs (rolling ptrs) -----------
        float xv_n = xv_c, mm_n = mm_c, dtv_n = dtv_c;
        float dt2_n[2] = {dt2_c[0], dt2_c[1]};
        if (t + 1 < T_) {
            if (tid < 48) { xv_n = xpA[13 + ac]; mm_n = xpA[19 + ac]; dtv_n = xpA[25]; }
            dt2_n[0] = pD0[13];
            dt2_n[1] = pD1[13];
        }

        // ---------------- Phase C: quarter's GEMV slice ----------------------
        ull aR[4], aZ[4], aGN[4], aIN[4], aP[4], aU[4];
        #pragma unroll
        for (int p = 0; p < 4; p++) { aR[p]=0; aZ[p]=0; aGN[p]=0; aIN[p]=0; aP[p]=0; aU[p]=0; }

        // input-to-hidden: 3 k-rows per quarter
        {
            int kin0 = q * 3;
            #pragma unroll
            for (int kk = 0; kk < 3; kk++) {
                int k = kin0 + kk;
                float4 wi = s_pI[k*H_ + j];
                ull wr = pk2(wi.x, wi.x), wz = pk2(wi.y, wi.y), wn = pk2(wi.z, wi.z);
                ulonglong2 gA = *(const ulonglong2*)(sh_gin + k*8);
                ulonglong2 gB = *(const ulonglong2*)(sh_gin + k*8 + 4);
                fma2(aR[0], gA.x, wr); fma2(aR[1], gA.y, wr); fma2(aR[2], gB.x, wr); fma2(aR[3], gB.y, wr);
                fma2(aZ[0], gA.x, wz); fma2(aZ[1], gA.y, wz); fma2(aZ[2], gB.x, wz); fma2(aZ[3], gB.y, wz);
                fma2(aIN[0],gA.x, wn); fma2(aIN[1],gA.y, wn); fma2(aIN[2],gB.x, wn); fma2(aIN[3],gB.y, wn);
            }
        }

        #define KROW(W4, KK) do {                                              \
            float4 wA = (W4);                                                  \
            ulonglong2 dA = *(const ulonglong2*)(sh_hd + (KK)*8);              \
            ulonglong2 dB = *(const ulonglong2*)(sh_hd + (KK)*8 + 4);          \
            ulonglong2 hA = *(const ulonglong2*)(sh_h  + (KK)*8);              \
            ulonglong2 hB = *(const ulonglong2*)(sh_h  + (KK)*8 + 4);          \
            ull wr = pk2(wA.x, wA.x), wz = pk2(wA.y, wA.y);                    \
            ull wn = pk2(wA.z, wA.z), wp = pk2(wA.w, wA.w);                    \
            fma2(aR[0],dA.x,wr);  fma2(aR[1],dA.y,wr);  fma2(aR[2],dB.x,wr);  fma2(aR[3],dB.y,wr);  \
            fma2(aZ[0],dA.x,wz);  fma2(aZ[1],dA.y,wz);  fma2(aZ[2],dB.x,wz);  fma2(aZ[3],dB.y,wz);  \
            fma2(aGN[0],dA.x,wn); fma2(aGN[1],dA.y,wn); fma2(aGN[2],dB.x,wn); fma2(aGN[3],dB.y,wn); \
            fma2(aP[0],hA.x,wp);  fma2(aP[1],hA.y,wp);  fma2(aP[2],hB.x,wp);  fma2(aP[3],hB.y,wp);  \
            if (j < 64) {                                                      \
                float wu = s_wu1[(KK)*64 + j];                                 \
                ull wup = pk2(wu, wu);                                         \
                fma2(aU[0],hA.x,wup); fma2(aU[1],hA.y,wup);                    \
                fma2(aU[2],hB.x,wup); fma2(aU[3],hB.y,wup);                    \
            }                                                                  \
        } while (0)

        // cached rows (smem)
        #pragma unroll 5
        for (int i = 0; i < KCQ; i++) KROW(wAp[i*H_], kg0 + i);
        // uncached rows (L2) — __ldg, unroll 4 for MLP
        #pragma unroll 4
        for (int i = 0; i < UCQ; i++) KROW(__ldg(&gAp[i*H_]), kg0 + KCQ + i);
        #undef KROW

        // ---------------- exchange partial sums (flat 4-way) -----------------
        {
            int w = 0;
            #pragma unroll
            for (int pp = 0; pp < 4; pp++) {
                if (pp == q) continue;
                ull* ws = s_part + wsOff[w++];
                ws[0*128] = aR[pp];  ws[1*128] = aZ[pp];  ws[2*128] = aGN[pp];
                ws[3*128] = aIN[pp]; ws[4*128] = aP[pp];  ws[5*128] = aU[pp];
            }
        }
        __syncthreads();   // barB
        #pragma unroll
        for (int s = 0; s < 3; s++) {
            const ull* rs = s_part + rsOff[s];
            add2(aR[q],  rs[0*128]);  add2(aZ[q], rs[1*128]);
            add2(aGN[q], rs[2*128]);  add2(aIN[q],rs[3*128]);
            add2(aP[q],  rs[4*128]);  add2(aU[q], rs[5*128]);
        }

        // ---------------- Phase D: gates + heads (own 2 batches) -------------
        {
            float2 vR = up2(aR[q]), vZ = up2(aZ[q]), vGN = up2(aGN[q]);
            float2 vIN = up2(aIN[q]), vP = up2(aP[q]), vU = up2(aU[q]);
            float fR[2]  = {vR.x, vR.y},  fZ[2] = {vZ.x, vZ.y};
            float fGN[2] = {vGN.x,vGN.y}, fIN[2]= {vIN.x,vIN.y};
            float fP[2]  = {vP.x, vP.y},  fU[2] = {vU.x, vU.y};
            #pragma unroll
            for (int lb = 0; lb < 2; lb++) {
                int gb = 2*q + lb;
                float r = sigf(fR[lb] + bihr + bhhr);
                float z = sigf(fZ[lb] + bihz + bhhz);
                float n = tanhfast(fIN[lb] + bihn + r * (fGN[lb] + bhhn));
                h_reg[lb] = n + z * (hdec[lb] - n);
                sh_hid1[gb*H_ + j] = fmaxf(fP[lb] + b1j, 0.f);   // heads of h(t-1)
                if (j < 64) sh_hidu[gb*64 + j] = fmaxf(fU[lb] + bu1j, 0.f);
            }
        }
        __syncthreads();   // barC: hid1/hidu ready

        // ---------------- Reduction: head layer-2, write outputs t-1 --------
        if (t >= 1) {
            if (tid < 48) {              // pred head
                float acc = b2c;
                const float* wrow = w2 + ac * H_;
                const float* hrow = sh_hid1 + ab * H_;
                #pragma unroll 2
                for (int k = 0; k < H_; k += 4) {
                    float4 hh = *(const float4*)(hrow + k);
                    float4 ww = *(const float4*)(wrow + k);
                    acc += hh.x*ww.x + hh.y*ww.y + hh.z*ww.z + hh.w*ww.w;
                }
                out[((size_t)(b0 + ab) * T_ + (t - 1)) * C_ + ac] = acc;
            } else if (ui >= 0 && ui < 48) {   // unc head
                float acc = bu2c;
                const float* wrow = wu2 + uc * 64;
                const float* hrow = sh_hidu + ub * 64;
                #pragma unroll 2
                for (int k = 0; k < 64; k += 4) {
                    float4 hh = *(const float4*)(hrow + k);
                    float4 ww = *(const float4*)(wrow + k);
                    acc += hh.x*ww.x + hh.y*ww.y + hh.z*ww.z + hh.w*ww.w;
                }
                float sp = fmaxf(acc, 0.f) + log1pf(__expf(-fabsf(acc)));  // softplus
                out[(size_t)B_*T_*C_ + ((size_t)(b0 + ub) * T_ + (t - 1)) * C_ + uc] = sp;
            }
        }

        // rotate prefetched inputs + advance rolling pointers
        xv_c = xv_n; mm_c = mm_n; dtv_c = dtv_n;
        dt2_c[0] = dt2_n[0]; dt2_c[1] = dt2_n[1];
        xpA += 13; pD0 += 13; pD1 += 13;
    }
}

extern "C" void kernel_launch(void* const* d_in, const int* in_sizes, int n_in,
                              void* d_out, int out_size) {
    const float* x      = (const float*)d_in[0];
    const float* x_mean = (const float*)d_in[1];
    const float* dxw    = (const float*)d_in[2];
    const float* dxb    = (const float*)d_in[3];
    const float* dhw    = (const float*)d_in[4];
    const float* dhb    = (const float*)d_in[5];
    const float* w_ih   = (const float*)d_in[6];
    const float* w_hh   = (const float*)d_in[7];
    const float* b_ih   = (const float*)d_in[8];
    const float* b_hh   = (const float*)d_in[9];
    const float* w1     = (const float*)d_in[10];
    const float* b1     = (const float*)d_in[11];
    const float* w2     = (const float*)d_in[12];
    const float* b2     = (const float*)d_in[13];
    const float* wu1    = (const float*)d_in[14];
    const float* bu1    = (const float*)d_in[15];
    const float* wu2    = (const float*)d_in[16];
    const float* bu2    = (const float*)d_in[17];
    float* out = (float*)d_out;

    // idempotent, not stream-captured; no static guards
    cudaFuncSetAttribute(grud_kernel, cudaFuncAttributeMaxDynamicSharedMemorySize, SMEM_BYTES);

    pack_kernel<<<NCTA, 128>>>(w_ih, w_hh, w1, wu1);
    grud_kernel<<<NCTA, NTHR, SMEM_BYTES>>>(x, x_mean, dxw, dxb, dhw, dhb,
                                            b_ih, b_hh, b1, w2, b2, bu1, wu2, bu2, out);
}

// round 9
// speedup vs baseline: 1.2661x; 1.2661x over previous
#include <cuda_runtime.h>
#include <cstdint>

typedef unsigned long long ull;

#define B_   1024
#define T_   1024
#define H_   128
#define C_   6
#define BPC  8            // batches per CTA
#define NCTA (B_/BPC)     // 128
#define KCH  33           // smem-cached packA rows PER HALF
#define UCH  (64-KCH)     // 31 uncached rows per half

// ---------------- packed transposed weights (device globals) ---------------
__device__ float4 g_packA[H_*H_];   // [k][j] = (whh_r, whh_z, whh_n, w1)[j][k]
__device__ float  g_wu1T[H_*64];    // [k][j] = wu1[j][k], j<64
__device__ float4 g_packI[12*H_];   // [k][j] = (wih_r, wih_z, wih_n, 0)[j][k]

// ---------------- f32x2 helpers --------------------------------------------
__device__ __forceinline__ ull pk2(float a, float b){
    ull r; asm("mov.b64 %0, {%1,%2};" : "=l"(r) : "f"(a), "f"(b)); return r;
}
__device__ __forceinline__ void fma2(ull& d, ull a, ull b){
    asm("fma.rn.f32x2 %0, %1, %2, %3;" : "=l"(d) : "l"(a), "l"(b), "l"(d));
}
__device__ __forceinline__ void add2(ull& d, ull a){
    asm("add.rn.f32x2 %0, %1, %2;" : "=l"(d) : "l"(d), "l"(a));
}
__device__ __forceinline__ float2 up2(ull v){
    float2 r; asm("mov.b64 {%0,%1}, %2;" : "=f"(r.x), "=f"(r.y) : "l"(v)); return r;
}
__device__ __forceinline__ float sigf(float x){
    return __fdividef(1.f, 1.f + __expf(-x));
}
__device__ __forceinline__ float tanhfast(float x){
    float e = __expf(-2.f * fabsf(x));
    float t = __fdividef(1.f - e, 1.f + e);
    return copysignf(t, x);
}

// ---------------- weight pack pre-pass -------------------------------------
__global__ void pack_kernel(const float* __restrict__ w_ih, const float* __restrict__ w_hh,
                            const float* __restrict__ w1,   const float* __restrict__ wu1){
    int idx = blockIdx.x * blockDim.x + threadIdx.x;   // 0..16383
    int k = idx >> 7, j = idx & 127;
    g_packA[idx] = make_float4(w_hh[j*H_ + k], w_hh[(j+H_)*H_ + k],
                               w_hh[(j+2*H_)*H_ + k], w1[j*H_ + k]);
    if (j < 64)  g_wu1T[k*64 + j] = wu1[j*H_ + k];
    if (k < 12)  g_packI[k*H_ + j] = make_float4(w_ih[j*12 + k], w_ih[(j+H_)*12 + k],
                                                 w_ih[(j+2*H_)*12 + k], 0.f);
}

// ---------------- dynamic smem layout (float offsets) -----------------------
#define OFF_H     0        // sh_h  [128 j][8 b]
#define OFF_HD    1024     // sh_hd [128 j][8 b]
#define OFF_GIN   2048     // sh_gin[12][8]
#define OFF_HID1  2144     // sh_hid1[8 b][128 j]
#define OFF_HIDU  3168     // sh_hidu[8 b][64 j]
#define OFF_WU1   3680     // s_wu1 [128 k][64 j]
#define OFF_PI    11872    // s_pI  [12 k][128 j] float4
#define OFF_PART  18016    // s_part: 2 halves x 12 slots x 128 j (ull)
#define OFF_WA    24160    // s_wA  [2*KCH][128] float4
#define SMEM_FLOATS (OFF_WA + 2*KCH*H_*4)
#define SMEM_BYTES  (SMEM_FLOATS * 4)   // 231,808 B <= 232,448

__global__ void __launch_bounds__(256, 1) grud_kernel(
    const float* __restrict__ x,
    const float* __restrict__ x_mean,
    const float* __restrict__ dxw, const float* __restrict__ dxb,
    const float* __restrict__ dhw, const float* __restrict__ dhb,
    const float* __restrict__ b_ih, const float* __restrict__ b_hh,
    const float* __restrict__ b1,
    const float* __restrict__ w2,  const float* __restrict__ b2,
    const float* __restrict__ bu1,
    const float* __restrict__ wu2, const float* __restrict__ bu2,
    float* __restrict__ out)
{
    extern __shared__ float smem[];
    float*  sh_h   = smem + OFF_H;
    float*  sh_hd  = smem + OFF_HD;
    float*  sh_gin = smem + OFF_GIN;
    float*  sh_hid1= smem + OFF_HID1;
    float*  sh_hidu= smem + OFF_HIDU;
    float*  s_wu1  = smem + OFF_WU1;
    float4* s_pI   = (float4*)(smem + OFF_PI);
    ull*    s_part = (ull*)  (smem + OFF_PART);
    float4* s_wA   = (float4*)(smem + OFF_WA);   // [half*KCH + local][128]

    const int tid  = threadIdx.x;
    const int half = tid >> 7;          // 0 -> k[0,64), 1 -> k[64,128)
    const int j    = tid & 127;
    const int b0   = blockIdx.x * BPC;
    const int oth  = 1 - half;

    // stage weights into shared (once)
    for (int i = tid; i < H_*64; i += 256) s_wu1[i] = g_wu1T[i];
    for (int i = tid; i < 12*H_; i += 256) s_pI[i]  = g_packI[i];
    for (int i = tid; i < 2*KCH*H_; i += 256) {
        int s = i >> 7, jj = i & 127;
        int row = (s < KCH) ? s : (s - KCH + 64);
        s_wA[i] = g_packA[row*H_ + jj];
    }

    // per-hidden-unit constants
    const float bihr = b_ih[j], bihz = b_ih[H_ + j], bihn = b_ih[2*H_ + j];
    const float bhhr = b_hh[j], bhhz = b_hh[H_ + j], bhhn = b_hh[2*H_ + j];
    const float b1j  = b1[j];
    const float bu1j = (j < 64) ? bu1[j] : 0.f;
    const float dhwj = dhw[j],  dhbj = dhb[j];

    // phase-A constants: tid<48 -> (batch ab, feature ac)
    const int ab = tid / 6, ac = tid - ab * 6;
    float xm = 0.f, axw = 0.f, axb = 0.f, b2c = 0.f;
    if (tid < 48) { xm = x_mean[ac]; axw = dxw[ac]; axb = dxb[ac]; b2c = b2[ac]; }
    // unc reducer: tid in [128,176) -> (ub, uc)
    const int ui = tid - 128;
    const int ub = ui / 6, uc = ui - ub * 6;
    float bu2c = 0.f;
    if (ui >= 0 && ui < 48) bu2c = bu2[uc];

    // rolling input pointers (advance by 13 per step)
    const float* xpA = x + (size_t)(b0 + ab) * T_ * 13;             // tid<48 path
    const float* pD[4];
    #pragma unroll
    for (int lb = 0; lb < 4; lb++)
        pD[lb] = x + (size_t)(b0 + half*4 + lb) * T_ * 13 + 12;     // own dt streams

    float running = 0.f, xlast = 0.f;
    float h_reg[4];                      // own 4 batches: gb = half*4 + lb
    #pragma unroll
    for (int lb = 0; lb < 4; lb++) h_reg[lb] = 0.f;

    // ---- preload step-0 inputs ---------------------------------------------
    float xv_c = 0.f, mm_c = 0.f, dtv_c = 0.f;
    if (tid < 48) { xv_c = xpA[ac]; mm_c = xpA[6 + ac]; dtv_c = xpA[12]; }
    float dt4_c[4];
    #pragma unroll
    for (int lb = 0; lb < 4; lb++) dt4_c[lb] = pD[lb][0];

    __syncthreads();   // staged weights ready

    const int kg0 = half * 64;
    const float4* wAp = s_wA + (size_t)(half*KCH)*H_ + j;            // cached rows
    const float4* gAp = g_packA + (size_t)(kg0 + KCH)*H_ + j;        // uncached rows

    for (int t = 0; t <= T_; ++t) {
        // ---------------- Phase A: impute inputs for step t -----------------
        if (t < T_ && tid < 48) {
            bool obs = (mm_c > 0.5f);
            running = obs ? 0.f : (running + dtv_c);
            float gx = __expf(-fmaxf(running * axw + axb, 0.f));
            xlast = obs ? xv_c : xlast;
            float xhat = mm_c * xv_c + (1.f - mm_c) * (gx * xlast + (1.f - gx) * xm);
            sh_gin[ac * 8 + ab]       = xhat;
            sh_gin[(6 + ac) * 8 + ab] = mm_c;
        }

        // ---------------- Phase B: decay own 4 batches, publish -------------
        float hdec[4];
        #pragma unroll
        for (int lb = 0; lb < 4; lb++) {
            float g = __expf(-fmaxf(dt4_c[lb] * dhwj + dhbj, 0.f));
            hdec[lb] = h_reg[lb] * g;
        }
        *(float4*)(sh_h  + j*8 + half*4) = make_float4(h_reg[0], h_reg[1], h_reg[2], h_reg[3]);
        *(float4*)(sh_hd + j*8 + half*4) = make_float4(hdec[0], hdec[1], hdec[2], hdec[3]);
        __syncthreads();   // barA: gin + h/hd ready

        // ---------------- prefetch step t+1 inputs (rolling ptrs) -----------
        float xv_n = xv_c, mm_n = mm_c, dtv_n = dtv_c;
        float dt4_n[4];
        #pragma unroll
        for (int lb = 0; lb < 4; lb++) dt4_n[lb] = dt4_c[lb];
        if (t + 1 < T_) {
            if (tid < 48) { xv_n = xpA[13 + ac]; mm_n = xpA[19 + ac]; dtv_n = xpA[25]; }
            #pragma unroll
            for (int lb = 0; lb < 4; lb++) dt4_n[lb] = pD[lb][13];
        }

        // ---------------- Phase C: k-split fused GEMV loops -----------------
        ull aR[4], aZ[4], aGN[4], aIN[4], aP[4], aU[4];
        #pragma unroll
        for (int p = 0; p < 4; p++) { aR[p]=0; aZ[p]=0; aGN[p]=0; aIN[p]=0; aP[p]=0; aU[p]=0; }

        // input-to-hidden (12 k, split 6/6)
        {
            int kin0 = half * 6;
            #pragma unroll
            for (int kk = 0; kk < 6; kk++) {
                int k = kin0 + kk;
                float4 wi = s_pI[k*H_ + j];
                ull wr = pk2(wi.x, wi.x), wz = pk2(wi.y, wi.y), wn = pk2(wi.z, wi.z);
                ulonglong2 gA = *(const ulonglong2*)(sh_gin + k*8);
                ulonglong2 gB = *(const ulonglong2*)(sh_gin + k*8 + 4);
                fma2(aR[0], gA.x, wr); fma2(aR[1], gA.y, wr); fma2(aR[2], gB.x, wr); fma2(aR[3], gB.y, wr);
                fma2(aZ[0], gA.x, wz); fma2(aZ[1], gA.y, wz); fma2(aZ[2], gB.x, wz); fma2(aZ[3], gB.y, wz);
                fma2(aIN[0],gA.x, wn); fma2(aIN[1],gA.y, wn); fma2(aIN[2],gB.x, wn); fma2(aIN[3],gB.y, wn);
            }
        }

        #define KROW(W4, KK) do {                                              \
            float4 wA = (W4);                                                  \
            ulonglong2 dA = *(const ulonglong2*)(sh_hd + (KK)*8);              \
            ulonglong2 dB = *(const ulonglong2*)(sh_hd + (KK)*8 + 4);          \
            ulonglong2 hA = *(const ulonglong2*)(sh_h  + (KK)*8);              \
            ulonglong2 hB = *(const ulonglong2*)(sh_h  + (KK)*8 + 4);          \
            ull wr = pk2(wA.x, wA.x), wz = pk2(wA.y, wA.y);                    \
            ull wn = pk2(wA.z, wA.z), wp = pk2(wA.w, wA.w);                    \
            fma2(aR[0],dA.x,wr);  fma2(aR[1],dA.y,wr);  fma2(aR[2],dB.x,wr);  fma2(aR[3],dB.y,wr);  \
            fma2(aZ[0],dA.x,wz);  fma2(aZ[1],dA.y,wz);  fma2(aZ[2],dB.x,wz);  fma2(aZ[3],dB.y,wz);  \
            fma2(aGN[0],dA.x,wn); fma2(aGN[1],dA.y,wn); fma2(aGN[2],dB.x,wn); fma2(aGN[3],dB.y,wn); \
            fma2(aP[0],hA.x,wp);  fma2(aP[1],hA.y,wp);  fma2(aP[2],hB.x,wp);  fma2(aP[3],hB.y,wp);  \
            if (j < 64) {                                                      \
                float wu = s_wu1[(KK)*64 + j];                                 \
                ull wup = pk2(wu, wu);                                         \
                fma2(aU[0],hA.x,wup); fma2(aU[1],hA.y,wup);                    \
                fma2(aU[2],hB.x,wup); fma2(aU[3],hB.y,wup);                    \
            }                                                                  \
        } while (0)

        // cached rows (smem)
        #pragma unroll 4
        for (int i = 0; i < KCH; i++) KROW(wAp[i*H_], kg0 + i);
        // uncached rows (L2): unroll 8 -> ptxas front-batches 8 LDG.128 (MLP~8)
        #pragma unroll 8
        for (int i = 0; i < UCH; i++) KROW(gAp[i*H_], kg0 + KCH + i);
        #undef KROW

        // ---------------- exchange partial sums -----------------------------
        {
            int fp = oth * 2;   // foreign pair base
            ull* wslot = s_part + (size_t)(half*12)*128 + j;
            wslot[0*128]  = aR[fp];   wslot[1*128]  = aR[fp+1];
            wslot[2*128]  = aZ[fp];   wslot[3*128]  = aZ[fp+1];
            wslot[4*128]  = aGN[fp];  wslot[5*128]  = aGN[fp+1];
            wslot[6*128]  = aIN[fp];  wslot[7*128]  = aIN[fp+1];
            wslot[8*128]  = aP[fp];   wslot[9*128]  = aP[fp+1];
            wslot[10*128] = aU[fp];   wslot[11*128] = aU[fp+1];
        }
        __syncthreads();   // barB
        {
            int op = half * 2;  // own pair base
            const ull* rslot = s_part + (size_t)(oth*12)*128 + j;
            add2(aR[op],  rslot[0*128]);  add2(aR[op+1],  rslot[1*128]);
            add2(aZ[op],  rslot[2*128]);  add2(aZ[op+1],  rslot[3*128]);
            add2(aGN[op], rslot[4*128]);  add2(aGN[op+1], rslot[5*128]);
            add2(aIN[op], rslot[6*128]);  add2(aIN[op+1], rslot[7*128]);
            add2(aP[op],  rslot[8*128]);  add2(aP[op+1],  rslot[9*128]);
            add2(aU[op],  rslot[10*128]); add2(aU[op+1],  rslot[11*128]);
        }

        // ---------------- Phase D: gates + head activations ------------------
        {
            int op = half * 2;
            float fR[4], fZ[4], fGN[4], fIN[4], fP[4], fU[4];
            float2 v;
            v = up2(aR[op]);    fR[0]=v.x;  fR[1]=v.y;
            v = up2(aR[op+1]);  fR[2]=v.x;  fR[3]=v.y;
            v = up2(aZ[op]);    fZ[0]=v.x;  fZ[1]=v.y;
            v = up2(aZ[op+1]);  fZ[2]=v.x;  fZ[3]=v.y;
            v = up2(aGN[op]);   fGN[0]=v.x; fGN[1]=v.y;
            v = up2(aGN[op+1]); fGN[2]=v.x; fGN[3]=v.y;
            v = up2(aIN[op]);   fIN[0]=v.x; fIN[1]=v.y;
            v = up2(aIN[op+1]); fIN[2]=v.x; fIN[3]=v.y;
            v = up2(aP[op]);    fP[0]=v.x;  fP[1]=v.y;
            v = up2(aP[op+1]);  fP[2]=v.x;  fP[3]=v.y;
            v = up2(aU[op]);    fU[0]=v.x;  fU[1]=v.y;
            v = up2(aU[op+1]);  fU[2]=v.x;  fU[3]=v.y;

            #pragma unroll
            for (int lb = 0; lb < 4; lb++) {
                int gb = half*4 + lb;
                float r = sigf(fR[lb] + bihr + bhhr);
                float z = sigf(fZ[lb] + bihz + bhhz);
                float n = tanhfast(fIN[lb] + bihn + r * (fGN[lb] + bhhn));
                h_reg[lb] = n + z * (hdec[lb] - n);
                sh_hid1[gb*H_ + j] = fmaxf(fP[lb] + b1j, 0.f);   // heads of h(t-1)
                if (j < 64) sh_hidu[gb*64 + j] = fmaxf(fU[lb] + bu1j, 0.f);
            }
        }
        __syncthreads();   // barC: hid1/hidu ready

        // ---------------- Reduction: head layer-2, write outputs t-1 --------
        if (t >= 1) {
            if (tid < 48) {              // pred head
                float acc = b2c;
                const float* wrow = w2 + ac * H_;
                const float* hrow = sh_hid1 + ab * H_;
                #pragma unroll 4
                for (int k = 0; k < H_; k += 4) {
                    float4 hh = *(const float4*)(hrow + k);
                    float4 ww = *(const float4*)(wrow + k);
                    acc += hh.x*ww.x + hh.y*ww.y + hh.z*ww.z + hh.w*ww.w;
                }
                out[((size_t)(b0 + ab) * T_ + (t - 1)) * C_ + ac] = acc;
            } else if (ui >= 0 && ui < 48) {   // unc head
                float acc = bu2c;
                const float* wrow = wu2 + uc * 64;
                const float* hrow = sh_hidu + ub * 64;
                #pragma unroll 4
                for (int k = 0; k < 64; k += 4) {
                    float4 hh = *(const float4*)(hrow + k);
                    float4 ww = *(const float4*)(wrow + k);
                    acc += hh.x*ww.x + hh.y*ww.y + hh.z*ww.z + hh.w*ww.w;
                }
                float sp = fmaxf(acc, 0.f) + log1pf(__expf(-fabsf(acc)));  // softplus
                out[(size_t)B_*T_*C_ + ((size_t)(b0 + ub) * T_ + (t - 1)) * C_ + uc] = sp;
            }
        }

        // rotate prefetched inputs + advance rolling pointers
        xv_c = xv_n; mm_c = mm_n; dtv_c = dtv_n;
        #pragma unroll
        for (int lb = 0; lb < 4; lb++) { dt4_c[lb] = dt4_n[lb]; pD[lb] += 13; }
        xpA += 13;
    }
}

extern "C" void kernel_launch(void* const* d_in, const int* in_sizes, int n_in,
                              void* d_out, int out_size) {
    const float* x      = (const float*)d_in[0];
    const float* x_mean = (const float*)d_in[1];
    const float* dxw    = (const float*)d_in[2];
    const float* dxb    = (const float*)d_in[3];
    const float* dhw    = (const float*)d_in[4];
    const float* dhb    = (const float*)d_in[5];
    const float* w_ih   = (const float*)d_in[6];
    const float* w_hh   = (const float*)d_in[7];
    const float* b_ih   = (const float*)d_in[8];
    const float* b_hh   = (const float*)d_in[9];
    const float* w1     = (const float*)d_in[10];
    const float* b1     = (const float*)d_in[11];
    const float* w2     = (const float*)d_in[12];
    const float* b2     = (const float*)d_in[13];
    const float* wu1    = (const float*)d_in[14];
    const float* bu1    = (const float*)d_in[15];
    const float* wu2    = (const float*)d_in[16];
    const float* bu2    = (const float*)d_in[17];
    float* out = (float*)d_out;

    // idempotent, not stream-captured; no static guards
    cudaFuncSetAttribute(grud_kernel, cudaFuncAttributeMaxDynamicSharedMemorySize, SMEM_BYTES);

    pack_kernel<<<NCTA, 128>>>(w_ih, w_hh, w1, wu1);
    grud_kernel<<<NCTA, 256, SMEM_BYTES>>>(x, x_mean, dxw, dxb, dhw, dhb,
                                           b_ih, b_hh, b1, w2, b2, bu1, wu2, bu2, out);
}

// round 10
// speedup vs baseline: 1.2712x; 1.0040x over previous
#include <cuda_runtime.h>
#include <cstdint>

typedef unsigned long long ull;

#define B_   1024
#define T_   1024
#define H_   128
#define C_   6
#define BPC  8            // batches per CTA
#define NCTA (B_/BPC)     // 128
#define KCH  33           // smem-cached packA rows PER HALF
#define UCH  (64-KCH)     // 31 uncached rows per half

// ---------------- packed transposed weights (device globals) ---------------
__device__ float4 g_packA[H_*H_];   // [k][j] = (whh_r, whh_z, whh_n, w1)[j][k]
__device__ float  g_wu1T[H_*64];    // [k][j] = wu1[j][k], j<64
__device__ float4 g_packI[12*H_];   // [k][j] = (wih_r, wih_z, wih_n, 0)[j][k]

// ---------------- f32x2 helpers --------------------------------------------
__device__ __forceinline__ ull pk2(float a, float b){
    ull r; asm("mov.b64 %0, {%1,%2};" : "=l"(r) : "f"(a), "f"(b)); return r;
}
__device__ __forceinline__ void fma2(ull& d, ull a, ull b){
    asm("fma.rn.f32x2 %0, %1, %2, %3;" : "=l"(d) : "l"(a), "l"(b), "l"(d));
}
__device__ __forceinline__ void add2(ull& d, ull a){
    asm("add.rn.f32x2 %0, %1, %2;" : "=l"(d) : "l"(d), "l"(a));
}
__device__ __forceinline__ float2 up2(ull v){
    float2 r; asm("mov.b64 {%0,%1}, %2;" : "=f"(r.x), "=f"(r.y) : "l"(v)); return r;
}
__device__ __forceinline__ float sigf(float x){
    return __fdividef(1.f, 1.f + __expf(-x));
}
__device__ __forceinline__ float tanhfast(float x){
    float e = __expf(-2.f * fabsf(x));
    float t = __fdividef(1.f - e, 1.f + e);
    return copysignf(t, x);
}

// ---------------- weight pack pre-pass -------------------------------------
__global__ void pack_kernel(const float* __restrict__ w_ih, const float* __restrict__ w_hh,
                            const float* __restrict__ w1,   const float* __restrict__ wu1){
    int idx = blockIdx.x * blockDim.x + threadIdx.x;   // 0..16383
    int k = idx >> 7, j = idx & 127;
    g_packA[idx] = make_float4(w_hh[j*H_ + k], w_hh[(j+H_)*H_ + k],
                               w_hh[(j+2*H_)*H_ + k], w1[j*H_ + k]);
    if (j < 64)  g_wu1T[k*64 + j] = wu1[j*H_ + k];
    if (k < 12)  g_packI[k*H_ + j] = make_float4(w_ih[j*12 + k], w_ih[(j+H_)*12 + k],
                                                 w_ih[(j+2*H_)*12 + k], 0.f);
}

// ---------------- dynamic smem layout (float offsets) -----------------------
#define OFF_H     0        // sh_h  [128 j][8 b]
#define OFF_HD    1024     // sh_hd [128 j][8 b]
#define OFF_GIN   2048     // sh_gin[12][8]
#define OFF_HID1  2144     // sh_hid1[8 b][128 j]
#define OFF_HIDU  3168     // sh_hidu[8 b][64 j]
#define OFF_WU1   3680     // s_wu1 [128 k][64 j]
#define OFF_PI    11872    // s_pI  [12 k][128 j] float4
#define OFF_PART  18016    // s_part: 2 halves x 12 slots x 128 j (ull)
#define OFF_WA    24160    // s_wA  [2*KCH][128] float4
#define SMEM_FLOATS (OFF_WA + 2*KCH*H_*4)
#define SMEM_BYTES  (SMEM_FLOATS * 4)   // 231,808 B <= 232,448

__global__ void __launch_bounds__(256, 1) grud_kernel(
    const float* __restrict__ x,
    const float* __restrict__ x_mean,
    const float* __restrict__ dxw, const float* __restrict__ dxb,
    const float* __restrict__ dhw, const float* __restrict__ dhb,
    const float* __restrict__ b_ih, const float* __restrict__ b_hh,
    const float* __restrict__ b1,
    const float* __restrict__ w2,  const float* __restrict__ b2,
    const float* __restrict__ bu1,
    const float* __restrict__ wu2, const float* __restrict__ bu2,
    float* __restrict__ out)
{
    extern __shared__ float smem[];
    float*  sh_h   = smem + OFF_H;
    float*  sh_hd  = smem + OFF_HD;
    float*  sh_gin = smem + OFF_GIN;
    float*  sh_hid1= smem + OFF_HID1;
    float*  sh_hidu= smem + OFF_HIDU;
    float*  s_wu1  = smem + OFF_WU1;
    float4* s_pI   = (float4*)(smem + OFF_PI);
    ull*    s_part = (ull*)  (smem + OFF_PART);
    float4* s_wA   = (float4*)(smem + OFF_WA);   // [half*KCH + local][128]

    const int tid  = threadIdx.x;
    const int half = tid >> 7;          // 0 -> k[0,64), 1 -> k[64,128)
    const int j    = tid & 127;
    const int b0   = blockIdx.x * BPC;
    const int oth  = 1 - half;

    // stage weights into shared (once)
    for (int i = tid; i < H_*64; i += 256) s_wu1[i] = g_wu1T[i];
    for (int i = tid; i < 12*H_; i += 256) s_pI[i]  = g_packI[i];
    for (int i = tid; i < 2*KCH*H_; i += 256) {
        int s = i >> 7, jj = i & 127;
        int row = (s < KCH) ? s : (s - KCH + 64);
        s_wA[i] = g_packA[row*H_ + jj];
    }

    // per-hidden-unit constants
    const float bihr = b_ih[j], bihz = b_ih[H_ + j], bihn = b_ih[2*H_ + j];
    const float bhhr = b_hh[j], bhhz = b_hh[H_ + j], bhhn = b_hh[2*H_ + j];
    const float b1j  = b1[j];
    const float bu1j = (j < 64) ? bu1[j] : 0.f;
    const float dhwj = dhw[j],  dhbj = dhb[j];

    // phase-A constants: tid<48 -> (batch ab, feature ac)
    const int ab = tid / 6, ac = tid - ab * 6;
    float xm = 0.f, axw = 0.f, axb = 0.f, b2c = 0.f;
    if (tid < 48) { xm = x_mean[ac]; axw = dxw[ac]; axb = dxb[ac]; b2c = b2[ac]; }
    // unc reducer: tid in [128,176) -> (ub, uc)
    const int ui = tid - 128;
    const int ub = ui / 6, uc = ui - ub * 6;
    float bu2c = 0.f;
    if (ui >= 0 && ui < 48) bu2c = bu2[uc];

    // rolling input pointers (advance by 13 per step)
    const float* xpA = x + (size_t)(b0 + ab) * T_ * 13;             // tid<48 path
    const float* pD[4];
    #pragma unroll
    for (int lb = 0; lb < 4; lb++)
        pD[lb] = x + (size_t)(b0 + half*4 + lb) * T_ * 13 + 12;     // own dt streams

    float running = 0.f, xlast = 0.f;
    float h_reg[4];                      // own 4 batches: gb = half*4 + lb
    #pragma unroll
    for (int lb = 0; lb < 4; lb++) h_reg[lb] = 0.f;

    // ---- preload step-0 inputs ---------------------------------------------
    float xv_c = 0.f, mm_c = 0.f, dtv_c = 0.f;
    if (tid < 48) { xv_c = xpA[ac]; mm_c = xpA[6 + ac]; dtv_c = xpA[12]; }
    float dt4_c[4];
    #pragma unroll
    for (int lb = 0; lb < 4; lb++) dt4_c[lb] = pD[lb][0];

    __syncthreads();   // staged weights ready

    const int kg0 = half * 64;
    const float4* wAp = s_wA + (size_t)(half*KCH)*H_ + j;            // cached rows
    const float4* gAp = g_packA + (size_t)(kg0 + KCH)*H_ + j;        // uncached rows

    for (int t = 0; t <= T_; ++t) {
        // ---------------- Phase A: impute inputs for step t -----------------
        if (t < T_ && tid < 48) {
            bool obs = (mm_c > 0.5f);
            running = obs ? 0.f : (running + dtv_c);
            float gx = __expf(-fmaxf(running * axw + axb, 0.f));
            xlast = obs ? xv_c : xlast;
            float xhat = mm_c * xv_c + (1.f - mm_c) * (gx * xlast + (1.f - gx) * xm);
            sh_gin[ac * 8 + ab]       = xhat;
            sh_gin[(6 + ac) * 8 + ab] = mm_c;
        }

        // ---------------- Phase B: decay own 4 batches, publish -------------
        float hdec[4];
        #pragma unroll
        for (int lb = 0; lb < 4; lb++) {
            float g = __expf(-fmaxf(dt4_c[lb] * dhwj + dhbj, 0.f));
            hdec[lb] = h_reg[lb] * g;
        }
        *(float4*)(sh_h  + j*8 + half*4) = make_float4(h_reg[0], h_reg[1], h_reg[2], h_reg[3]);
        *(float4*)(sh_hd + j*8 + half*4) = make_float4(hdec[0], hdec[1], hdec[2], hdec[3]);
        __syncthreads();   // barA: gin + h/hd ready

        // ---------------- prefetch step t+1 inputs (rolling ptrs) -----------
        float xv_n = xv_c, mm_n = mm_c, dtv_n = dtv_c;
        float dt4_n[4];
        #pragma unroll
        for (int lb = 0; lb < 4; lb++) dt4_n[lb] = dt4_c[lb];
        if (t + 1 < T_) {
            if (tid < 48) { xv_n = xpA[13 + ac]; mm_n = xpA[19 + ac]; dtv_n = xpA[25]; }
            #pragma unroll
            for (int lb = 0; lb < 4; lb++) dt4_n[lb] = pD[lb][13];
        }

        // ---------------- Phase C: k-split fused GEMV loops -----------------
        ull aR[4], aZ[4], aGN[4], aIN[4], aP[4], aU[4];
        #pragma unroll
        for (int p = 0; p < 4; p++) { aR[p]=0; aZ[p]=0; aGN[p]=0; aIN[p]=0; aP[p]=0; aU[p]=0; }

        // input-to-hidden (12 k, split 6/6)
        {
            int kin0 = half * 6;
            #pragma unroll
            for (int kk = 0; kk < 6; kk++) {
                int k = kin0 + kk;
                float4 wi = s_pI[k*H_ + j];
                ull wr = pk2(wi.x, wi.x), wz = pk2(wi.y, wi.y), wn = pk2(wi.z, wi.z);
                ulonglong2 gA = *(const ulonglong2*)(sh_gin + k*8);
                ulonglong2 gB = *(const ulonglong2*)(sh_gin + k*8 + 4);
                fma2(aR[0], gA.x, wr); fma2(aR[1], gA.y, wr); fma2(aR[2], gB.x, wr); fma2(aR[3], gB.y, wr);
                fma2(aZ[0], gA.x, wz); fma2(aZ[1], gA.y, wz); fma2(aZ[2], gB.x, wz); fma2(aZ[3], gB.y, wz);
                fma2(aIN[0],gA.x, wn); fma2(aIN[1],gA.y, wn); fma2(aIN[2],gB.x, wn); fma2(aIN[3],gB.y, wn);
            }
        }

        #define KROW(W4, KK) do {                                              \
            float4 wA = (W4);                                                  \
            ulonglong2 dA = *(const ulonglong2*)(sh_hd + (KK)*8);              \
            ulonglong2 dB = *(const ulonglong2*)(sh_hd + (KK)*8 + 4);          \
            ulonglong2 hA = *(const ulonglong2*)(sh_h  + (KK)*8);              \
            ulonglong2 hB = *(const ulonglong2*)(sh_h  + (KK)*8 + 4);          \
            ull wr = pk2(wA.x, wA.x), wz = pk2(wA.y, wA.y);                    \
            ull wn = pk2(wA.z, wA.z), wp = pk2(wA.w, wA.w);                    \
            fma2(aR[0],dA.x,wr);  fma2(aR[1],dA.y,wr);  fma2(aR[2],dB.x,wr);  fma2(aR[3],dB.y,wr);  \
            fma2(aZ[0],dA.x,wz);  fma2(aZ[1],dA.y,wz);  fma2(aZ[2],dB.x,wz);  fma2(aZ[3],dB.y,wz);  \
            fma2(aGN[0],dA.x,wn); fma2(aGN[1],dA.y,wn); fma2(aGN[2],dB.x,wn); fma2(aGN[3],dB.y,wn); \
            fma2(aP[0],hA.x,wp);  fma2(aP[1],hA.y,wp);  fma2(aP[2],hB.x,wp);  fma2(aP[3],hB.y,wp);  \
            if (j < 64) {                                                      \
                float wu = s_wu1[(KK)*64 + j];                                 \
                ull wup = pk2(wu, wu);                                         \
                fma2(aU[0],hA.x,wup); fma2(aU[1],hA.y,wup);                    \
                fma2(aU[2],hB.x,wup); fma2(aU[3],hB.y,wup);                    \
            }                                                                  \
        } while (0)

        // cached rows (smem)
        #pragma unroll 4
        for (int i = 0; i < KCH; i++) KROW(wAp[i*H_], kg0 + i);
        // uncached rows (L2): unroll 8 -> ptxas front-batches 8 LDG.128 (MLP~8)
        #pragma unroll 8
        for (int i = 0; i < UCH; i++) KROW(gAp[i*H_], kg0 + KCH + i);
        #undef KROW

        // ---------------- exchange partial sums -----------------------------
        {
            int fp = oth * 2;   // foreign pair base
            ull* wslot = s_part + (size_t)(half*12)*128 + j;
            wslot[0*128]  = aR[fp];   wslot[1*128]  = aR[fp+1];
            wslot[2*128]  = aZ[fp];   wslot[3*128]  = aZ[fp+1];
            wslot[4*128]  = aGN[fp];  wslot[5*128]  = aGN[fp+1];
            wslot[6*128]  = aIN[fp];  wslot[7*128]  = aIN[fp+1];
            wslot[8*128]  = aP[fp];   wslot[9*128]  = aP[fp+1];
            wslot[10*128] = aU[fp];   wslot[11*128] = aU[fp+1];
        }
        __syncthreads();   // barB
        {
            int op = half * 2;  // own pair base
            const ull* rslot = s_part + (size_t)(oth*12)*128 + j;
            add2(aR[op],  rslot[0*128]);  add2(aR[op+1],  rslot[1*128]);
            add2(aZ[op],  rslot[2*128]);  add2(aZ[op+1],  rslot[3*128]);
            add2(aGN[op], rslot[4*128]);  add2(aGN[op+1], rslot[5*128]);
            add2(aIN[op], rslot[6*128]);  add2(aIN[op+1], rslot[7*128]);
            add2(aP[op],  rslot[8*128]);  add2(aP[op+1],  rslot[9*128]);
            add2(aU[op],  rslot[10*128]); add2(aU[op+1],  rslot[11*128]);
        }

        // ---------------- Phase D: gates + head activations ------------------
        {
            int op = half * 2;
            float fR[4], fZ[4], fGN[4], fIN[4], fP[4], fU[4];
            float2 v;
            v = up2(aR[op]);    fR[0]=v.x;  fR[1]=v.y;
            v = up2(aR[op+1]);  fR[2]=v.x;  fR[3]=v.y;
            v = up2(aZ[op]);    fZ[0]=v.x;  fZ[1]=v.y;
            v = up2(aZ[op+1]);  fZ[2]=v.x;  fZ[3]=v.y;
            v = up2(aGN[op]);   fGN[0]=v.x; fGN[1]=v.y;
            v = up2(aGN[op+1]); fGN[2]=v.x; fGN[3]=v.y;
            v = up2(aIN[op]);   fIN[0]=v.x; fIN[1]=v.y;
            v = up2(aIN[op+1]); fIN[2]=v.x; fIN[3]=v.y;
            v = up2(aP[op]);    fP[0]=v.x;  fP[1]=v.y;
            v = up2(aP[op+1]);  fP[2]=v.x;  fP[3]=v.y;
            v = up2(aU[op]);    fU[0]=v.x;  fU[1]=v.y;
            v = up2(aU[op+1]);  fU[2]=v.x;  fU[3]=v.y;

            #pragma unroll
            for (int lb = 0; lb < 4; lb++) {
                int gb = half*4 + lb;
                float r = sigf(fR[lb] + bihr + bhhr);
                float z = sigf(fZ[lb] + bihz + bhhz);
                float n = tanhfast(fIN[lb] + bihn + r * (fGN[lb] + bhhn));
                h_reg[lb] = n + z * (hdec[lb] - n);
                sh_hid1[gb*H_ + j] = fmaxf(fP[lb] + b1j, 0.f);   // heads of h(t-1)
                if (j < 64) sh_hidu[gb*64 + j] = fmaxf(fU[lb] + bu1j, 0.f);
            }
        }
        __syncthreads();   // barC: hid1/hidu ready

        // ---------------- Reduction: head layer-2, write outputs t-1 --------
        if (t >= 1) {
            if (tid < 48) {              // pred head
                float acc = b2c;
                const float* wrow = w2 + ac * H_;
                const float* hrow = sh_hid1 + ab * H_;
                #pragma unroll 4
                for (int k = 0; k < H_; k += 4) {
                    float4 hh = *(const float4*)(hrow + k);
                    float4 ww = *(const float4*)(wrow + k);
                    acc += hh.x*ww.x + hh.y*ww.y + hh.z*ww.z + hh.w*ww.w;
                }
                out[((size_t)(b0 + ab) * T_ + (t - 1)) * C_ + ac] = acc;
            } else if (ui >= 0 && ui < 48) {   // unc head
                float acc = bu2c;
                const float* wrow = wu2 + uc * 64;
                const float* hrow = sh_hidu + ub * 64;
                #pragma unroll 4
                for (int k = 0; k < 64; k += 4) {
                    float4 hh = *(const float4*)(hrow + k);
                    float4 ww = *(const float4*)(wrow + k);
                    acc += hh.x*ww.x + hh.y*ww.y + hh.z*ww.z + hh.w*ww.w;
                }
                float sp = fmaxf(acc, 0.f) + log1pf(__expf(-fabsf(acc)));  // softplus
                out[(size_t)B_*T_*C_ + ((size_t)(b0 + ub) * T_ + (t - 1)) * C_ + uc] = sp;
            }
        }

        // rotate prefetched inputs + advance rolling pointers
        xv_c = xv_n; mm_c = mm_n; dtv_c = dtv_n;
        #pragma unroll
        for (int lb = 0; lb < 4; lb++) { dt4_c[lb] = dt4_n[lb]; pD[lb] += 13; }
        xpA += 13;
    }
}

extern "C" void kernel_launch(void* const* d_in, const int* in_sizes, int n_in,
                              void* d_out, int out_size) {
    const float* x      = (const float*)d_in[0];
    const float* x_mean = (const float*)d_in[1];
    const float* dxw    = (const float*)d_in[2];
    const float* dxb    = (const float*)d_in[3];
    const float* dhw    = (const float*)d_in[4];
    const float* dhb    = (const float*)d_in[5];
    const float* w_ih   = (const float*)d_in[6];
    const float* w_hh   = (const float*)d_in[7];
    const float* b_ih   = (const float*)d_in[8];
    const float* b_hh   = (const float*)d_in[9];
    const float* w1     = (const float*)d_in[10];
    const float* b1     = (const float*)d_in[11];
    const float* w2     = (const float*)d_in[12];
    const float* b2     = (const float*)d_in[13];
    const float* wu1    = (const float*)d_in[14];
    const float* bu1    = (const float*)d_in[15];
    const float* wu2    = (const float*)d_in[16];
    const float* bu2    = (const float*)d_in[17];
    float* out = (float*)d_out;

    // idempotent, not stream-captured; no static guards
    cudaFuncSetAttribute(grud_kernel, cudaFuncAttributeMaxDynamicSharedMemorySize, SMEM_BYTES);

    pack_kernel<<<NCTA, 128>>>(w_ih, w_hh, w1, wu1);
    grud_kernel<<<NCTA, 256, SMEM_BYTES>>>(x, x_mean, dxw, dxb, dhw, dhb,
                                           b_ih, b_hh, b1, w2, b2, bu1, wu2, bu2, out);
}

// round 11
// speedup vs baseline: 1.4494x; 1.1402x over previous
#include <cuda_runtime.h>
#include <cstdint>

typedef unsigned long long ull;

#define B_   1024
#define T_   1024
#define H_   128
#define C_   6
#define BPC  8            // batches per CTA
#define NCTA (B_/BPC)     // 128
#define NTHR 384          // 8 gate warps (256) + 4 head warps (128)
#define KCH2 32           // cached packA rows per gate half (of 64)

// ---------------- packed transposed weights (device globals) ---------------
__device__ float4 g_packA[H_*H_];   // [k][j] = (whh_r, whh_z, whh_n, w1)[j][k]
__device__ float  g_w1T [H_*H_];    // [k][j] = w1[j][k]  (compact, for head streaming)
__device__ float  g_wu1T[H_*64];    // [k][u] = wu1[u][k]
__device__ float4 g_packI[12*H_];   // [k][j] = (wih_r, wih_z, wih_n, 0)[j][k]

// ---------------- f32x2 helpers --------------------------------------------
__device__ __forceinline__ ull pk2(float a, float b){
    ull r; asm("mov.b64 %0, {%1,%2};" : "=l"(r) : "f"(a), "f"(b)); return r;
}
__device__ __forceinline__ void fma2(ull& d, ull a, ull b){
    asm("fma.rn.f32x2 %0, %1, %2, %3;" : "=l"(d) : "l"(a), "l"(b), "l"(d));
}
__device__ __forceinline__ void add2(ull& d, ull a){
    asm("add.rn.f32x2 %0, %1, %2;" : "=l"(d) : "l"(d), "l"(a));
}
__device__ __forceinline__ float2 up2(ull v){
    float2 r; asm("mov.b64 {%0,%1}, %2;" : "=f"(r.x), "=f"(r.y) : "l"(v)); return r;
}
__device__ __forceinline__ float sigf(float x){
    return __fdividef(1.f, 1.f + __expf(-x));
}
__device__ __forceinline__ float tanhfast(float x){
    float e = __expf(-2.f * fabsf(x));
    float t = __fdividef(1.f - e, 1.f + e);
    return copysignf(t, x);
}
#define BARG() asm volatile("bar.sync 1, 256;" ::: "memory")   // gate warps only
#define BARH() asm volatile("bar.sync 2, 128;" ::: "memory")   // head warps only

// ---------------- weight pack pre-pass -------------------------------------
__global__ void pack_kernel(const float* __restrict__ w_ih, const float* __restrict__ w_hh,
                            const float* __restrict__ w1,   const float* __restrict__ wu1){
    int idx = blockIdx.x * blockDim.x + threadIdx.x;   // 0..16383
    int k = idx >> 7, j = idx & 127;
    g_packA[idx] = make_float4(w_hh[j*H_ + k], w_hh[(j+H_)*H_ + k],
                               w_hh[(j+2*H_)*H_ + k], w1[j*H_ + k]);
    g_w1T[idx] = w1[j*H_ + k];
    if (j < 64)  g_wu1T[k*64 + j] = wu1[j*H_ + k];
    if (k < 12)  g_packI[k*H_ + j] = make_float4(w_ih[j*12 + k], w_ih[(j+H_)*12 + k],
                                                 w_ih[(j+2*H_)*12 + k], 0.f);
}

// ---------------- dynamic smem layout (float offsets) -----------------------
#define OFF_H     0        // sh_h  [2][128 j][8 b]   (2048)
#define OFF_HD    2048     // sh_hd [2][128 j][8 b]   (2048)
#define OFF_GIN   4096     // sh_gin[2][12][8] padded to 128 each (256)
#define OFF_HID1  4352     // sh_hid1[8 b][128 j]     (1024)
#define OFF_HIDU  5376     // sh_hidu[8 b][64 u]      (512)
#define OFF_UPART 5888     // u-partials: 4 ull x 64 u (512)
#define OFF_PART  6400     // gate exchange: 2 halves x 8 slots x 128 j ull (4096)
#define OFF_WU1   10496    // s_wu1 [128 k][64 u]     (8192)
#define OFF_PI    18688    // s_pI  [12 k][128 j] float4 (6144)
#define OFF_WA    24832    // s_wA  [2*KCH2][128 j] float4 (32768)
#define SMEM_FLOATS (OFF_WA + 2*KCH2*H_*4)
#define SMEM_BYTES  (SMEM_FLOATS * 4)   // 230,400 B <= 232,448

__global__ void __launch_bounds__(NTHR, 1) grud_kernel(
    const float* __restrict__ x,
    const float* __restrict__ x_mean,
    const float* __restrict__ dxw, const float* __restrict__ dxb,
    const float* __restrict__ dhw, const float* __restrict__ dhb,
    const float* __restrict__ b_ih, const float* __restrict__ b_hh,
    const float* __restrict__ b1,
    const float* __restrict__ w2,  const float* __restrict__ b2,
    const float* __restrict__ bu1,
    const float* __restrict__ wu2, const float* __restrict__ bu2,
    float* __restrict__ out)
{
    extern __shared__ float smem[];
    float*  sh_hid1= smem + OFF_HID1;
    float*  sh_hidu= smem + OFF_HIDU;
    ull*    s_upart= (ull*)(smem + OFF_UPART);
    ull*    s_part = (ull*)(smem + OFF_PART);
    float*  s_wu1  = smem + OFF_WU1;
    float4* s_pI   = (float4*)(smem + OFF_PI);
    float4* s_wA   = (float4*)(smem + OFF_WA);   // rows [0,32)∪[64,96) of packA

    const int tid = threadIdx.x;
    const int b0  = blockIdx.x * BPC;
    const bool isGate = (tid < 256);

    // ---- stage weights into shared (all threads) ----------------------------
    for (int i = tid; i < H_*64; i += NTHR) s_wu1[i] = g_wu1T[i];
    for (int i = tid; i < 12*H_; i += NTHR) s_pI[i]  = g_packI[i];
    for (int i = tid; i < 2*KCH2*H_; i += NTHR) {
        int s = i >> 7, jj = i & 127;
        int row = (s < KCH2) ? s : (s - KCH2 + 64);   // rows 0..31 and 64..95
        s_wA[i] = g_packA[row*H_ + jj];
    }
    // zero buffer 0 of h / hd
    for (int i = tid; i < 1024; i += NTHR) { smem[OFF_H + i] = 0.f; smem[OFF_HD + i] = 0.f; }

    // ======================= per-role constants ==============================
    // gate role
    const int half = (tid >> 7) & 1;      // 0/1 for tid<256
    const int j    = tid & 127;
    // head role
    const int hj    = tid - 256;          // 0..127 when head
    const int u     = hj & 63;
    const int khalf = hj >> 6;            // warp-uniform

    float bihr=0,bihz=0,bihn=0,bhhr=0,bhhz=0,bhhn=0,dhwj=0,dhbj=0;
    if (isGate) {
        bihr=b_ih[j]; bihz=b_ih[H_+j]; bihn=b_ih[2*H_+j];
        bhhr=b_hh[j]; bhhz=b_hh[H_+j]; bhhn=b_hh[2*H_+j];
        dhwj=dhw[j];  dhbj=dhb[j];
    }
    float b1h=0, bu1u=0;
    if (!isGate) { b1h = b1[hj]; bu1u = bu1[u]; }

    // phase-A constants: tid<48 -> (batch ab, feature ac)
    const int ab = tid / 6, ac = tid - ab * 6;
    float xm=0, axw=0, axb=0;
    if (tid < 48) { xm = x_mean[ac]; axw = dxw[ac]; axb = dxb[ac]; }
    // head reducers: hj<48 -> pred (pb,pc); hj in [64,112) -> unc (ub,uc)
    const int pb = hj / 6, pc = hj - pb * 6;
    const int vi = hj - 64;
    const int ub = vi / 6, uc = vi - ub * 6;
    float b2c=0, bu2c=0;
    if (!isGate && hj < 48) b2c = b2[pc];
    if (!isGate && vi >= 0 && vi < 48) bu2c = bu2[uc];

    // rolling input pointers
    const float* xpA = x + (size_t)(b0 + ab) * T_ * 13;   // phase A (tid<48)
    const float* pD  = x + (size_t)(b0 + half*4) * T_ * 13 + 12;  // own dt base
    const size_t DST = (size_t)T_ * 13;                   // batch stride

    float running = 0.f, xlast = 0.f;
    float hdecP[4] = {0.f, 0.f, 0.f, 0.f};   // own hdec for current step (gate)
    float dtn[4]   = {0.f, 0.f, 0.f, 0.f};

    // ---- pre-loop: phase A for t=0 into gin buf 0 ---------------------------
    if (tid < 48) {
        float xv = xpA[ac], mm = xpA[6+ac], dtv = xpA[12];
        bool obs = (mm > 0.5f);
        running = obs ? 0.f : (running + dtv);
        float gx = __expf(-fmaxf(running * axw + axb, 0.f));
        xlast = obs ? xv : xlast;
        float xhat = mm*xv + (1.f-mm)*(gx*xlast + (1.f-gx)*xm);
        smem[OFF_GIN + ac*8 + ab]     = xhat;
        smem[OFF_GIN + (6+ac)*8 + ab] = mm;
    }

    const int kg0 = half * 64;
    const float4* wAg = s_wA + (size_t)(half*KCH2)*H_ + j;             // cached gate rows
    const float4* gAg = g_packA + (size_t)(kg0 + KCH2)*H_ + j;         // streamed gate rows

    for (int t = 0; t <= T_; ++t) {
        __syncthreads();
        const int c = t & 1, nb = c ^ 1;
        float* sh_hc  = smem + OFF_H  + c*1024;
        float* sh_hdc = smem + OFF_HD + c*1024;

        if (isGate) {
            if (t < T_) {
                // ---- phase A for step t+1 -> gin[nb] ------------------------
                if (t + 1 < T_ && tid < 48) {
                    const float* xp = xpA + (size_t)(t+1)*13;
                    float xv = xp[ac], mm = xp[6+ac], dtv = xp[12];
                    bool obs = (mm > 0.5f);
                    running = obs ? 0.f : (running + dtv);
                    float gx = __expf(-fmaxf(running * axw + axb, 0.f));
                    xlast = obs ? xv : xlast;
                    float xhat = mm*xv + (1.f-mm)*(gx*xlast + (1.f-gx)*xm);
                    smem[OFF_GIN + nb*128 + ac*8 + ab]     = xhat;
                    smem[OFF_GIN + nb*128 + (6+ac)*8 + ab] = mm;
                }
                // ---- dt(t+1) for own 4 batches ------------------------------
                if (t + 1 < T_) {
                    const float* pdt = pD + (size_t)(t+1)*13;
                    #pragma unroll
                    for (int lb = 0; lb < 4; lb++) dtn[lb] = pdt[lb*DST];
                }

                // ---- gate GEMV slice (R,Z,GN from sh_hd; IN from gin) -------
                ull aR[4], aZ[4], aGN[4], aIN[4];
                #pragma unroll
                for (int p = 0; p < 4; p++) { aR[p]=0; aZ[p]=0; aGN[p]=0; aIN[p]=0; }

                {
                    const float* ginc = smem + OFF_GIN + c*128;
                    int kin0 = half * 6;
                    #pragma unroll
                    for (int kk = 0; kk < 6; kk++) {
                        int k = kin0 + kk;
                        float4 wi = s_pI[k*H_ + j];
                        ull wr = pk2(wi.x,wi.x), wz = pk2(wi.y,wi.y), wn = pk2(wi.z,wi.z);
                        ulonglong2 gA = *(const ulonglong2*)(ginc + k*8);
                        ulonglong2 gB = *(const ulonglong2*)(ginc + k*8 + 4);
                        fma2(aR[0],gA.x,wr); fma2(aR[1],gA.y,wr); fma2(aR[2],gB.x,wr); fma2(aR[3],gB.y,wr);
                        fma2(aZ[0],gA.x,wz); fma2(aZ[1],gA.y,wz); fma2(aZ[2],gB.x,wz); fma2(aZ[3],gB.y,wz);
                        fma2(aIN[0],gA.x,wn);fma2(aIN[1],gA.y,wn);fma2(aIN[2],gB.x,wn);fma2(aIN[3],gB.y,wn);
                    }
                }

                #define GKROW(W4, KK) do {                                       \
                    float4 wA = (W4);                                            \
                    ulonglong2 dA = *(const ulonglong2*)(sh_hdc + (KK)*8);       \
                    ulonglong2 dB = *(const ulonglong2*)(sh_hdc + (KK)*8 + 4);   \
                    ull wr = pk2(wA.x,wA.x), wz = pk2(wA.y,wA.y), wn = pk2(wA.z,wA.z); \
                    fma2(aR[0],dA.x,wr);  fma2(aR[1],dA.y,wr);  fma2(aR[2],dB.x,wr);  fma2(aR[3],dB.y,wr);  \
                    fma2(aZ[0],dA.x,wz);  fma2(aZ[1],dA.y,wz);  fma2(aZ[2],dB.x,wz);  fma2(aZ[3],dB.y,wz);  \
                    fma2(aGN[0],dA.x,wn); fma2(aGN[1],dA.y,wn); fma2(aGN[2],dB.x,wn); fma2(aGN[3],dB.y,wn); \
                } while (0)

                #pragma unroll 4
                for (int i = 0; i < KCH2; i++)      GKROW(wAg[i*H_], kg0 + i);
                #pragma unroll 8
                for (int i = 0; i < 64-KCH2; i++)   GKROW(gAg[i*H_], kg0 + KCH2 + i);
                #undef GKROW

                // ---- exchange partials (gate-only barrier) ------------------
                {
                    int fp = (1 - half) * 2;
                    ull* ws = s_part + (size_t)(half*8)*128 + j;
                    ws[0*128] = aR[fp];  ws[1*128] = aR[fp+1];
                    ws[2*128] = aZ[fp];  ws[3*128] = aZ[fp+1];
                    ws[4*128] = aGN[fp]; ws[5*128] = aGN[fp+1];
                    ws[6*128] = aIN[fp]; ws[7*128] = aIN[fp+1];
                }
                BARG();
                int op = half * 2;
                {
                    const ull* rs = s_part + (size_t)((1-half)*8)*128 + j;
                    add2(aR[op],  rs[0*128]); add2(aR[op+1],  rs[1*128]);
                    add2(aZ[op],  rs[2*128]); add2(aZ[op+1],  rs[3*128]);
                    add2(aGN[op], rs[4*128]); add2(aGN[op+1], rs[5*128]);
                    add2(aIN[op], rs[6*128]); add2(aIN[op+1], rs[7*128]);
                }

                // ---- gates + h update + next decay --------------------------
                float fR[4], fZ[4], fGN[4], fIN[4];
                float2 v;
                v = up2(aR[op]);    fR[0]=v.x;  fR[1]=v.y;
                v = up2(aR[op+1]);  fR[2]=v.x;  fR[3]=v.y;
                v = up2(aZ[op]);    fZ[0]=v.x;  fZ[1]=v.y;
                v = up2(aZ[op+1]);  fZ[2]=v.x;  fZ[3]=v.y;
                v = up2(aGN[op]);   fGN[0]=v.x; fGN[1]=v.y;
                v = up2(aGN[op+1]); fGN[2]=v.x; fGN[3]=v.y;
                v = up2(aIN[op]);   fIN[0]=v.x; fIN[1]=v.y;
                v = up2(aIN[op+1]); fIN[2]=v.x; fIN[3]=v.y;

                float hNew[4], hdN[4];
                #pragma unroll
                for (int lb = 0; lb < 4; lb++) {
                    float r = sigf(fR[lb] + bihr + bhhr);
                    float z = sigf(fZ[lb] + bihz + bhhz);
                    float n = tanhfast(fIN[lb] + bihn + r * (fGN[lb] + bhhn));
                    hNew[lb] = n + z * (hdecP[lb] - n);
                    float g = __expf(-fmaxf(dtn[lb] * dhwj + dhbj, 0.f));
                    hdN[lb] = hNew[lb] * g;
                }
                *(float4*)(smem + OFF_H  + nb*1024 + j*8 + half*4) = make_float4(hNew[0],hNew[1],hNew[2],hNew[3]);
                *(float4*)(smem + OFF_HD + nb*1024 + j*8 + half*4) = make_float4(hdN[0],hdN[1],hdN[2],hdN[3]);
                #pragma unroll
                for (int lb = 0; lb < 4; lb++) hdecP[lb] = hdN[lb];
            }
        } else {
            if (t >= 1) {
                // ---- head GEMV on h(t-1) = sh_hc ----------------------------
                ull aP[4], aU[4];
                #pragma unroll
                for (int p = 0; p < 4; p++) { aP[p]=0; aU[p]=0; }

                #define PROW(WEXPR, KK) do {                                     \
                    float wpv = (WEXPR); ull wp = pk2(wpv, wpv);                 \
                    ulonglong2 hA = *(const ulonglong2*)(sh_hc + (KK)*8);        \
                    ulonglong2 hB = *(const ulonglong2*)(sh_hc + (KK)*8 + 4);    \
                    fma2(aP[0],hA.x,wp); fma2(aP[1],hA.y,wp);                    \
                    fma2(aP[2],hB.x,wp); fma2(aP[3],hB.y,wp);                    \
                } while (0)
                #define PUROW(WEXPR, KK) do {                                    \
                    float wpv = (WEXPR); ull wp = pk2(wpv, wpv);                 \
                    float wuv = s_wu1[(KK)*64 + u]; ull wu_ = pk2(wuv, wuv);     \
                    ulonglong2 hA = *(const ulonglong2*)(sh_hc + (KK)*8);        \
                    ulonglong2 hB = *(const ulonglong2*)(sh_hc + (KK)*8 + 4);    \
                    fma2(aP[0],hA.x,wp);  fma2(aP[1],hA.y,wp);                   \
                    fma2(aP[2],hB.x,wp);  fma2(aP[3],hB.y,wp);                   \
                    fma2(aU[0],hA.x,wu_); fma2(aU[1],hA.y,wu_);                  \
                    fma2(aU[2],hB.x,wu_); fma2(aU[3],hB.y,wu_);                  \
                } while (0)

                if (khalf == 0) {   // U over k in [0,64)
                    #pragma unroll 4
                    for (int k = 0; k < 32; k++)   PUROW(s_wA[k*H_ + hj].w, k);
                    #pragma unroll 8
                    for (int k = 32; k < 64; k++)  PUROW(__ldg(g_w1T + k*H_ + hj), k);
                    #pragma unroll 4
                    for (int k = 64; k < 96; k++)  PROW(s_wA[(k-32)*H_ + hj].w, k);
                    #pragma unroll 8
                    for (int k = 96; k < 128; k++) PROW(__ldg(g_w1T + k*H_ + hj), k);
                } else {            // U over k in [64,128)
                    #pragma unroll 4
                    for (int k = 0; k < 32; k++)   PROW(s_wA[k*H_ + hj].w, k);
                    #pragma unroll 8
                    for (int k = 32; k < 64; k++)  PROW(__ldg(g_w1T + k*H_ + hj), k);
                    #pragma unroll 4
                    for (int k = 64; k < 96; k++)  PUROW(s_wA[(k-32)*H_ + hj].w, k);
                    #pragma unroll 8
                    for (int k = 96; k < 128; k++) PUROW(__ldg(g_w1T + k*H_ + hj), k);
                }
                #undef PROW
                #undef PUROW

                // hid1 = relu(P + b1): 8 batches for this hj
                {
                    float2 v;
                    #pragma unroll
                    for (int p = 0; p < 4; p++) {
                        v = up2(aP[p]);
                        sh_hid1[(2*p  )*H_ + hj] = fmaxf(v.x + b1h, 0.f);
                        sh_hid1[(2*p+1)*H_ + hj] = fmaxf(v.y + b1h, 0.f);
                    }
                }
                // U partials from khalf==1 threads
                if (khalf == 1) {
                    #pragma unroll
                    for (int p = 0; p < 4; p++) s_upart[p*64 + u] = aU[p];
                }
                BARH();
                if (khalf == 0) {
                    float2 v;
                    #pragma unroll
                    for (int p = 0; p < 4; p++) {
                        add2(aU[p], s_upart[p*64 + u]);
                        v = up2(aU[p]);
                        sh_hidu[(2*p  )*64 + u] = fmaxf(v.x + bu1u, 0.f);
                        sh_hidu[(2*p+1)*64 + u] = fmaxf(v.y + bu1u, 0.f);
                    }
                }
                // pred reduction (hid1 ready)
                if (hj < 48) {
                    float acc = b2c;
                    const float* wrow = w2 + pc * H_;
                    const float* hrow = sh_hid1 + pb * H_;
                    #pragma unroll 4
                    for (int k = 0; k < H_; k += 4) {
                        float4 hh = *(const float4*)(hrow + k);
                        float4 ww = *(const float4*)(wrow + k);
                        acc += hh.x*ww.x + hh.y*ww.y + hh.z*ww.z + hh.w*ww.w;
                    }
                    out[((size_t)(b0 + pb) * T_ + (t - 1)) * C_ + pc] = acc;
                }
                BARH();   // hidu ready
                if (vi >= 0 && vi < 48) {
                    float acc = bu2c;
                    const float* wrow = wu2 + uc * 64;
                    const float* hrow = sh_hidu + ub * 64;
                    #pragma unroll 4
                    for (int k = 0; k < 64; k += 4) {
                        float4 hh = *(const float4*)(hrow + k);
                        float4 ww = *(const float4*)(wrow + k);
                        acc += hh.x*ww.x + hh.y*ww.y + hh.z*ww.z + hh.w*ww.w;
                    }
                    float sp = fmaxf(acc, 0.f) + log1pf(__expf(-fabsf(acc)));
                    out[(size_t)B_*T_*C_ + ((size_t)(b0 + ub) * T_ + (t - 1)) * C_ + uc] = sp;
                }
            }
        }
    }
}

extern "C" void kernel_launch(void* const* d_in, const int* in_sizes, int n_in,
                              void* d_out, int out_size) {
    const float* x      = (const float*)d_in[0];
    const float* x_mean = (const float*)d_in[1];
    const float* dxw    = (const float*)d_in[2];
    const float* dxb    = (const float*)d_in[3];
    const float* dhw    = (const float*)d_in[4];
    const float* dhb    = (const float*)d_in[5];
    const float* w_ih   = (const float*)d_in[6];
    const float* w_hh   = (const float*)d_in[7];
    const float* b_ih   = (const float*)d_in[8];
    const float* b_hh   = (const float*)d_in[9];
    const float* w1     = (const float*)d_in[10];
    const float* b1     = (const float*)d_in[11];
    const float* w2     = (const float*)d_in[12];
    const float* b2     = (const float*)d_in[13];
    const float* wu1    = (const float*)d_in[14];
    const float* bu1    = (const float*)d_in[15];
    const float* wu2    = (const float*)d_in[16];
    const float* bu2    = (const float*)d_in[17];
    float* out = (float*)d_out;

    // idempotent, not stream-captured; no static guards
    cudaFuncSetAttribute(grud_kernel, cudaFuncAttributeMaxDynamicSharedMemorySize, SMEM_BYTES);

    pack_kernel<<<NCTA, 128>>>(w_ih, w_hh, w1, wu1);
    grud_kernel<<<NCTA, NTHR, SMEM_BYTES>>>(x, x_mean, dxw, dxb, dhw, dhb,
                                            b_ih, b_hh, b1, w2, b2, bu1, wu2, bu2, out);
}